// round 15
// baseline (speedup 1.0000x reference)
#include <cuda_runtime.h>
#include <cstdint>

#define NTOK   2048
#define DMODEL 512
#define DFFN   2048
#define NH     8
#define DHEAD  64
#define NLAYER 6

// ---------------- device scratch (static, no allocation) ----------------
__device__ float g_X[NTOK * DMODEL];
__device__ float g_QKV[3 * NTOK * DMODEL];               // Q | K | V planes
__device__ float2 g_part[NH * 16 * NTOK];                // lse partials (2 MB)
__device__ float g_corr[NH * DHEAD];
__device__ float g_bvec[DMODEL];                         // corr @ WO
__device__ float g_KVp[NH * 32 * DHEAD * DHEAD];         // K^T V partials (4 MB)
__device__ float g_Wc[DMODEL * DMODEL];                  // blockdiag(G) @ WO (1 MB)
__device__ float g_Z[NTOK * DMODEL];
__device__ float g_F[NTOK * DFFN];
__device__ float g_P[4 * NTOK * DMODEL];                 // split-K partials (16 MB)

// ---------------- fast exp (FMA-only, no MUFU) ----------------
__device__ __forceinline__ float fexp(float x) {
    x = fmaxf(x, -87.0f);
    float t = x * 1.4426950408889634f;
    const float big = 12582912.0f;
    float r = __fadd_rn(t, big) - big;
    float f = t - r;
    float p = 1.5403530e-4f;
    p = fmaf(p, f, 1.33335581e-3f);
    p = fmaf(p, f, 9.61812911e-3f);
    p = fmaf(p, f, 5.55041087e-2f);
    p = fmaf(p, f, 2.40226507e-1f);
    p = fmaf(p, f, 6.93147181e-1f);
    p = fmaf(p, f, 1.0f);
    int e = (int)r;
    return p * __int_as_float((e + 127) << 23);
}

// ---------------- bf16 / mma helpers ----------------
__device__ __forceinline__ uint32_t packbf(float e0, float e1) {  // e0 -> bits[15:0]
    uint32_t r;
    asm("cvt.rn.bf16x2.f32 %0, %1, %2;" : "=r"(r) : "f"(e1), "f"(e0));
    return r;
}
__device__ __forceinline__ float lo_f(uint32_t p) { return __uint_as_float(p << 16); }
__device__ __forceinline__ float hi_f(uint32_t p) { return __uint_as_float(p & 0xffff0000u); }

__device__ __forceinline__ void cvt_store4(char* hiP, char* loP, float4 v) {
    uint32_t h01 = packbf(v.x, v.y), h23 = packbf(v.z, v.w);
    uint32_t l01 = packbf(v.x - lo_f(h01), v.y - hi_f(h01));
    uint32_t l23 = packbf(v.z - lo_f(h23), v.w - hi_f(h23));
    *(uint2*)hiP = make_uint2(h01, h23);
    *(uint2*)loP = make_uint2(l01, l23);
}

__device__ __forceinline__ void ldsm4(uint32_t r[4], uint32_t addr) {
    asm volatile("ldmatrix.sync.aligned.m8n8.x4.shared.b16 {%0,%1,%2,%3}, [%4];"
                 : "=r"(r[0]), "=r"(r[1]), "=r"(r[2]), "=r"(r[3]) : "r"(addr));
}
__device__ __forceinline__ void ldsm4t(uint32_t r[4], uint32_t addr) {
    asm volatile("ldmatrix.sync.aligned.m8n8.x4.trans.shared.b16 {%0,%1,%2,%3}, [%4];"
                 : "=r"(r[0]), "=r"(r[1]), "=r"(r[2]), "=r"(r[3]) : "r"(addr));
}
__device__ __forceinline__ void mma_bf16(float d[4], const uint32_t a[4],
                                         uint32_t b0, uint32_t b1) {
    asm volatile(
        "mma.sync.aligned.m16n8k16.row.col.f32.bf16.bf16.f32 "
        "{%0,%1,%2,%3}, {%4,%5,%6,%7}, {%8,%9}, {%0,%1,%2,%3};"
        : "+f"(d[0]), "+f"(d[1]), "+f"(d[2]), "+f"(d[3])
        : "r"(a[0]), "r"(a[1]), "r"(a[2]), "r"(a[3]), "r"(b0), "r"(b1));
}

// ---------------- embedding + positional encoding ----------------
__global__ void embed_pe(const int* __restrict__ ids, const float* __restrict__ E,
                         float* __restrict__ X) {
    int n = blockIdx.x, t = threadIdx.x;                  // 128 threads
    int id = ids[n];
    float4 e = *(const float4*)&E[(size_t)id * DMODEL + t * 4];
    float ev[4] = {e.x, e.y, e.z, e.w};
    float pos = (float)(n + 1);
    float ov[4];
#pragma unroll
    for (int i = 0; i < 4; i++) {
        int d = t * 4 + i;
        int de = d & ~1;
        float f = expf((float)de * (-9.210340371976184f / 512.0f));
        float arg = pos * f;
        float pe = (d & 1) ? cosf(arg) : sinf(arg);
        ov[i] = ev[i] + pe;
    }
    *(float4*)&X[(size_t)n * DMODEL + t * 4] = *(float4*)ov;
}

// ---------------- bf16x3 tensor-core GEMM (champion single-buffer mainloop) ----------------
// NN only. C = alpha*A*B + bias + res, optional relu; or raw partials (split-K).
// BM=128, BN=64, BK=32; 256 threads / 8 warps; warp tile 32x32.
template <bool RELU, bool QKV, bool SPLITK>
__global__ void __launch_bounds__(256, 2)
gemm_tc(const float* __restrict__ Ag, const float* __restrict__ Bg,
        float* __restrict__ Cg, int K, int lda, int ldb, int ldc,
        long long sA, long long sB, long long sC,
        const float* __restrict__ biasg, int sBias,
        const float* __restrict__ resg, int ldr, long long sR,
        float alpha,
        const float* __restrict__ Bg1, const float* __restrict__ Bg2,
        float* __restrict__ Pbuf, int nsplit, int zInner) {
    __shared__ __align__(16) char sm[20480 + 8192];       // A hi/lo 2x10240, B hi/lo 2x4096
    char* Ahi = sm;
    char* Alo = sm + 10240;
    char* Bhi = sm + 20480;
    char* Blo = sm + 20480 + 4096;

    const int tid = threadIdx.x;
    const int bz = blockIdx.z;
    int bzIn = bz, split = 0;
    if (SPLITK) { bzIn = bz % zInner; split = bz / zInner; }
    const int kLen = SPLITK ? K / nsplit : K;
    const int kStart = SPLITK ? split * kLen : 0;

    const float* A = Ag + (size_t)bzIn * sA + (size_t)blockIdx.y * 128 * lda + kStart;
    const float* B;
    if (QKV) {
        int op = bz >> 3;
        const float* Bsel = (op == 0) ? Bg : (op == 1 ? Bg1 : Bg2);
        B = Bsel + (size_t)(bz & 7) * sB;
    } else {
        B = Bg + (size_t)bzIn * sB + (size_t)kStart * ldb + (size_t)blockIdx.x * 64;
    }

    const int ar = tid >> 3, ac = tid & 7;                // A loader coords
    const int kk_ld = tid >> 4, nb4 = (tid & 15) * 4;     // B loader coords

    float4 aR[4], bR[2];

    auto ldgA = [&](int k0) {
#pragma unroll
        for (int i = 0; i < 4; i++)
            aR[i] = *(const float4*)&A[(size_t)(ar + i * 32) * lda + k0 + ac * 4];
    };
    auto ldgB = [&](int k0) {
#pragma unroll
        for (int i = 0; i < 2; i++)
            bR[i] = *(const float4*)&B[(size_t)(k0 + kk_ld + i * 16) * ldb + nb4];
    };
    auto stsA = [&]() {
#pragma unroll
        for (int i = 0; i < 4; i++) {
            int off = (ar + i * 32) * 80 + ac * 8;        // 80B-pitch rows
            cvt_store4(Ahi + off, Alo + off, aR[i]);
        }
    };
    auto stsB = [&]() {
#pragma unroll
        for (int i = 0; i < 2; i++) {
            int k = kk_ld + i * 16;                       // [k][n] 128B rows, swizzled
            int off = k * 128 + (((nb4 >> 3) ^ (k & 7)) << 4) + ((nb4 & 4) << 1);
            cvt_store4(Bhi + off, Blo + off, bR[i]);
        }
    };

    const int lane = tid & 31, warp = tid >> 5;
    const int wm = (warp & 3) << 5, wn = (warp >> 2) << 5;
    uint32_t sm_u = (uint32_t)__cvta_generic_to_shared(sm);
    const uint32_t aBase = sm_u + (uint32_t)((wm + (lane & 15)) * 80 + (lane >> 4) * 16);
    const int krowL = (lane & 7) + ((lane >> 4) << 3);
    const int chnkL = (wn >> 3) + ((lane >> 3) & 1);

    float d[2][4][4];
#pragma unroll
    for (int i = 0; i < 2; i++)
#pragma unroll
        for (int j = 0; j < 4; j++)
#pragma unroll
            for (int q = 0; q < 4; q++) d[i][j][q] = 0.f;

    ldgA(0); ldgB(0);
    stsA(); stsB();
    __syncthreads();

    const int nkt = kLen >> 5;
    for (int kt = 0; kt < nkt; kt++) {
        if (kt + 1 < nkt) { ldgA((kt + 1) << 5); ldgB((kt + 1) << 5); }
#pragma unroll
        for (int ks = 0; ks < 2; ks++) {
            uint32_t ah[2][4], al[2][4], bh[2][4], bl[2][4];
#pragma unroll
            for (int mb = 0; mb < 2; mb++) {
                uint32_t a = aBase + (uint32_t)(mb * 16 * 80 + ks * 32);
                ldsm4(ah[mb], a);
                ldsm4(al[mb], a + 10240u);
            }
#pragma unroll
            for (int g = 0; g < 2; g++) {
                int k = ks * 16 + krowL;
                uint32_t b = sm_u + 20480u +
                             (uint32_t)(k * 128 + (((chnkL + g * 2) ^ (k & 7)) << 4));
                ldsm4t(bh[g], b);
                ldsm4t(bl[g], b + 4096u);
            }
#pragma unroll
            for (int mb = 0; mb < 2; mb++)
#pragma unroll
                for (int nb = 0; nb < 4; nb++) {
                    int g = nb >> 1, j = nb & 1;
                    uint32_t B0 = bh[g][j], B1 = bh[g][j + 2];
                    mma_bf16(d[mb][nb], ah[mb], B0, B1);
                    mma_bf16(d[mb][nb], ah[mb], bl[g][j], bl[g][j + 2]);
                    mma_bf16(d[mb][nb], al[mb], B0, B1);
                }
        }
        __syncthreads();
        if (kt + 1 < nkt) { stsA(); stsB(); __syncthreads(); }
    }

    const int gr = lane >> 2, gc = (lane & 3) * 2;
    const int mBase = blockIdx.y * 128 + wm;
    const int nBase = blockIdx.x * 64 + wn;
    if (SPLITK) {
        const int Mfull = gridDim.y * 128, Nfull = gridDim.x * 64;
        float* P = Pbuf + (size_t)(split * zInner + bzIn) * Mfull * Nfull;
#pragma unroll
        for (int mb = 0; mb < 2; mb++)
#pragma unroll
            for (int nb = 0; nb < 4; nb++)
#pragma unroll
                for (int h2 = 0; h2 < 2; h2++) {
                    int m = mBase + mb * 16 + gr + h2 * 8;
                    int n = nBase + nb * 8 + gc;
                    *(float2*)&P[(size_t)m * Nfull + n] =
                        make_float2(d[mb][nb][h2 * 2] * alpha, d[mb][nb][h2 * 2 + 1] * alpha);
                }
        return;
    }
    float* C;
    if (QKV) {
        C = Cg + (size_t)(bz >> 3) * (NTOK * DMODEL) + (size_t)(bz & 7) * 64;
    } else {
        C = Cg + (size_t)bzIn * sC;
    }
    const float* bi = biasg ? biasg + (size_t)bzIn * sBias : nullptr;
    const float* Rg = resg ? resg + (size_t)bzIn * sR : nullptr;
#pragma unroll
    for (int mb = 0; mb < 2; mb++)
#pragma unroll
        for (int nb = 0; nb < 4; nb++)
#pragma unroll
            for (int h2 = 0; h2 < 2; h2++) {
                int m = mBase + mb * 16 + gr + h2 * 8;
                int n = nBase + nb * 8 + gc;
                float v0 = d[mb][nb][h2 * 2] * alpha;
                float v1 = d[mb][nb][h2 * 2 + 1] * alpha;
                if (bi) {
                    float2 bb = *(const float2*)&bi[n];
                    v0 += bb.x; v1 += bb.y;
                }
                if (Rg) {
                    float2 rr = *(const float2*)&Rg[(size_t)m * ldr + n];
                    v0 += rr.x; v1 += rr.y;
                }
                if (RELU) { v0 = fmaxf(v0, 0.f); v1 = fmaxf(v1, 0.f); }
                *(float2*)&C[(size_t)m * ldc + n] = make_float2(v0, v1);
            }
}

// ---------------- fused QK^T tile + column (max, sumexp) partials (bf16 compute) --------
__global__ void __launch_bounds__(256, 2)
qk_lse(const float* __restrict__ Qg, const float* __restrict__ Kg,
       float2* __restrict__ part) {
    __shared__ __align__(16) char sm[128 * 144 + 64 * 144];   // A 18432B | B 9216B
    char* Asm = sm;
    char* Bsm = sm + 128 * 144;

    const int tid = threadIdx.x;
    const int h = blockIdx.z;
    const float* A = Qg + h * 64 + (size_t)blockIdx.y * 128 * DMODEL;
    const float* B = Kg + h * 64 + (size_t)blockIdx.x * 64 * DMODEL;

    // load + convert: A = 2048 float4, B = 1024 float4
#pragma unroll
    for (int r = 0; r < 8; r++) {
        int idx = tid + r * 256;                          // 0..2047
        int row = idx >> 4, c4 = (idx & 15) * 4;
        float4 v = *(const float4*)&A[(size_t)row * DMODEL + c4];
        *(uint2*)(Asm + row * 144 + c4 * 2) =
            make_uint2(packbf(v.x, v.y), packbf(v.z, v.w));
    }
#pragma unroll
    for (int r = 0; r < 4; r++) {
        int idx = tid + r * 256;                          // 0..1023
        int row = idx >> 4, c4 = (idx & 15) * 4;
        float4 v = *(const float4*)&B[(size_t)row * DMODEL + c4];
        *(uint2*)(Bsm + row * 144 + c4 * 2) =
            make_uint2(packbf(v.x, v.y), packbf(v.z, v.w));
    }
    __syncthreads();

    const int lane = tid & 31, warp = tid >> 5;
    const int wm = (warp & 3) << 5, wn = (warp >> 2) << 5;
    uint32_t sm_u = (uint32_t)__cvta_generic_to_shared(sm);
    const uint32_t aBase = sm_u + (uint32_t)((wm + (lane & 15)) * 144 + (lane >> 4) * 16);
    const uint32_t bBase = sm_u + (uint32_t)(128 * 144) +
                           (uint32_t)((wn + (lane & 15)) * 144 + (lane >> 4) * 16);

    float d[2][4][4];
#pragma unroll
    for (int i = 0; i < 2; i++)
#pragma unroll
        for (int j = 0; j < 4; j++)
#pragma unroll
            for (int q = 0; q < 4; q++) d[i][j][q] = 0.f;

#pragma unroll
    for (int ks = 0; ks < 4; ks++) {
        uint32_t ah[2][4], bh[2][4];
#pragma unroll
        for (int mb = 0; mb < 2; mb++)
            ldsm4(ah[mb], aBase + (uint32_t)(mb * 16 * 144 + ks * 32));
#pragma unroll
        for (int g = 0; g < 2; g++)
            ldsm4(bh[g], bBase + (uint32_t)(g * 16 * 144 + ks * 32));
#pragma unroll
        for (int mb = 0; mb < 2; mb++)
#pragma unroll
            for (int nb = 0; nb < 4; nb++) {
                int g = nb >> 1, j = nb & 1;
                mma_bf16(d[mb][nb], ah[mb], bh[g][j], bh[g][j + 2]);
            }
    }

    // ---- per-column (max, sumexp) over this block's 128 q-rows ----
    const int gc0 = (lane & 3) * 2;
    float cm[8], cs[8];
#pragma unroll
    for (int idx = 0; idx < 8; idx++) {
        int nb = idx >> 1, j = idx & 1;
        float v0 = d[0][nb][j] * 0.125f;
        float v1 = d[0][nb][2 + j] * 0.125f;
        float v2 = d[1][nb][j] * 0.125f;
        float v3 = d[1][nb][2 + j] * 0.125f;
        float m = fmaxf(fmaxf(v0, v1), fmaxf(v2, v3));
        cm[idx] = m;
        cs[idx] = fexp(v0 - m) + fexp(v1 - m) + fexp(v2 - m) + fexp(v3 - m);
    }
#pragma unroll
    for (int off = 4; off <= 16; off <<= 1) {
#pragma unroll
        for (int idx = 0; idx < 8; idx++) {
            float om = __shfl_xor_sync(0xffffffffu, cm[idx], off);
            float os = __shfl_xor_sync(0xffffffffu, cs[idx], off);
            float nm = fmaxf(cm[idx], om);
            cs[idx] = cs[idx] * fexp(cm[idx] - nm) + os * fexp(om - nm);
            cm[idx] = nm;
        }
    }
    __syncthreads();
    float2* psm = (float2*)sm;                            // [4][64], aliases mainloop smem
    if (lane < 4) {
#pragma unroll
        for (int idx = 0; idx < 8; idx++) {
            int nb = idx >> 1, j = idx & 1;
            int col = wn + gc0 + j + nb * 8;
            psm[(warp & 3) * 64 + col] = make_float2(cm[idx], cs[idx]);
        }
    }
    __syncthreads();
    if (tid < 64) {
        float2 a = psm[tid];
        float m = a.x, s = a.y;
#pragma unroll
        for (int w = 1; w < 4; w++) {
            float2 b = psm[w * 64 + tid];
            float nm = fmaxf(m, b.x);
            s = s * fexp(m - nm) + b.y * fexp(b.x - nm);
            m = nm;
        }
        part[((size_t)h * 16 + blockIdx.y) * NTOK + blockIdx.x * 64 + tid] =
            make_float2(m, s);
    }
}

// ---------------- fused lse-combine + corr: corr[h][v] = -sum_m lse[h,m] V[m,h64+v] ----
__global__ void lse_corr_kernel(const float2* __restrict__ part,
                                const float* __restrict__ Vb,
                                float* __restrict__ corr) {
    const int h = blockIdx.x, t = threadIdx.x;            // 256 threads
    __shared__ float slse[NTOK];
    __shared__ float red[256];
#pragma unroll
    for (int i = 0; i < 8; i++) {
        int m = t + 256 * i;
        float mx = -3.0e38f;
        float2 p[16];
#pragma unroll
        for (int s = 0; s < 16; s++) {
            p[s] = part[((size_t)h * 16 + s) * NTOK + m];
            mx = fmaxf(mx, p[s].x);
        }
        float sum = 0.f;
#pragma unroll
        for (int s = 0; s < 16; s++) sum += p[s].y * expf(p[s].x - mx);
        slse[m] = mx + logf(sum);
    }
    __syncthreads();
    int v = t & 63, seg = t >> 6;
    const float* Vp = Vb + h * 64 + v;
    float acc = 0.f;
    for (int m = seg * 512; m < seg * 512 + 512; m++)
        acc = fmaf(slse[m], Vp[(size_t)m * DMODEL], acc);
    red[t] = acc;
    __syncthreads();
    if (t < 64) {
        float tot = red[t] + red[t + 64] + red[t + 128] + red[t + 192];
        corr[h * 64 + t] = -tot;
    }
}

// ---------------- K^T V rank-update partials: per (head, m-chunk of 64) ----------------
// 32-row smem stages (2 stages, 4 barriers); grid 256 blocks for full-chip spread.
__global__ void __launch_bounds__(256)
ktv_kernel(const float* __restrict__ Kg, const float* __restrict__ Vg,
           float* __restrict__ Pk) {
    const int chunk = blockIdx.x, h = blockIdx.y;         // 32 chunks x 8 heads
    const int tid = threadIdx.x;
    const int td = tid & 15, tv = tid >> 4;               // 16x16 thread grid, 4x4 tiles
    __shared__ float sk[32][64], sv[32][64];
    const float* Kp = Kg + h * 64;
    const float* Vp = Vg + h * 64;
    const int m0 = chunk * 64;

    float acc[4][4];
#pragma unroll
    for (int i = 0; i < 4; i++)
#pragma unroll
        for (int j = 0; j < 4; j++) acc[i][j] = 0.f;

    for (int mb = 0; mb < 64; mb += 32) {
        __syncthreads();
#pragma unroll
        for (int r = 0; r < 2; r++) {
            int i = tid + r * 256;                        // float4 index 0..511
            int mi = i >> 4, c4 = (i & 15) * 4;
            *(float4*)&sk[mi][c4] =
                *(const float4*)&Kp[(size_t)(m0 + mb + mi) * DMODEL + c4];
            *(float4*)&sv[mi][c4] =
                *(const float4*)&Vp[(size_t)(m0 + mb + mi) * DMODEL + c4];
        }
        __syncthreads();
#pragma unroll 8
        for (int mi = 0; mi < 32; mi++) {
            float4 kk = *(const float4*)&sk[mi][td * 4];
            float4 vv = *(const float4*)&sv[mi][tv * 4];
            float ka[4] = {kk.x, kk.y, kk.z, kk.w};
            float va[4] = {vv.x, vv.y, vv.z, vv.w};
#pragma unroll
            for (int i = 0; i < 4; i++)
#pragma unroll
                for (int j = 0; j < 4; j++)
                    acc[i][j] = fmaf(ka[i], va[j], acc[i][j]);
        }
    }
    float* P = Pk + ((size_t)h * 32 + chunk) * (DHEAD * DHEAD);
#pragma unroll
    for (int i = 0; i < 4; i++)
        *(float4*)&P[(td * 4 + i) * 64 + tv * 4] = *(float4*)acc[i];
}

// ---------------- Wc = blockdiag(G) @ WO (G reduced from 32 KVp chunks in-kernel),
//                  plus bvec = corr @ WO (jt==8 branch) ----------
__global__ void __launch_bounds__(256)
gwo_kernel(const float* __restrict__ KVp, const float* __restrict__ WO,
           float* __restrict__ Wc, const float* __restrict__ corr,
           float* __restrict__ bvec) {
    const int jt = blockIdx.x, h = blockIdx.y;            // (9 x 8) blocks
    const int tid = threadIdx.x;
    __shared__ float sg[64][65];
    __shared__ float sw[64][68];

    if (jt == 8) {
        // bvec[h*64 + c] = sum_i corr[i] * WO[i][h*64 + c]
        float* red = &sg[0][0];
        int c = tid & 63, seg = tid >> 6;
        float acc = 0.f;
        for (int i = seg * 128; i < seg * 128 + 128; i++)
            acc = fmaf(corr[i], WO[(size_t)i * DMODEL + h * 64 + c], acc);
        red[tid] = acc;
        __syncthreads();
        if (tid < 64)
            bvec[h * 64 + tid] = red[tid] + red[tid + 64] + red[tid + 128] + red[tid + 192];
        return;
    }

    const int tj = tid & 15, td = tid >> 4;
    const float* Pk = KVp + (size_t)h * 32 * 4096;
#pragma unroll
    for (int r = 0; r < 16; r++) {
        int i = tid + r * 256;
        int row = i >> 6, c = i & 63;
        float v = Pk[i];                                  // chunk 0
#pragma unroll 4
        for (int ch = 1; ch < 32; ch++) v += Pk[(size_t)ch * 4096 + i];
        sg[row][c] = v * 0.125f;                          // = G[h][row][c]
        sw[row][c] = WO[(size_t)(h * 64 + row) * DMODEL + jt * 64 + c];
    }
    __syncthreads();
    float acc[4][4];
#pragma unroll
    for (int i = 0; i < 4; i++)
#pragma unroll
        for (int j = 0; j < 4; j++) acc[i][j] = 0.f;
#pragma unroll 8
    for (int v = 0; v < 64; v++) {
        float a[4], w[4];
#pragma unroll
        for (int i = 0; i < 4; i++) a[i] = sg[td * 4 + i][v];
        float4 w4 = *(const float4*)&sw[v][tj * 4];
        w[0] = w4.x; w[1] = w4.y; w[2] = w4.z; w[3] = w4.w;
#pragma unroll
        for (int i = 0; i < 4; i++)
#pragma unroll
            for (int j = 0; j < 4; j++)
                acc[i][j] = fmaf(a[i], w[j], acc[i][j]);
    }
#pragma unroll
    for (int i = 0; i < 4; i++)
        *(float4*)&Wc[(size_t)(h * 64 + td * 4 + i) * DMODEL + jt * 64 + tj * 4] =
            *(float4*)acc[i];
}

// ---------------- fused split-K reduce + bias + residual + layernorm ----------------
__global__ void __launch_bounds__(128)
reduce_ln(const float* __restrict__ P, int nsplit,
          const float* __restrict__ bias, const float* __restrict__ res,
          const float* __restrict__ g, const float* __restrict__ be,
          float* __restrict__ out) {
    int n = blockIdx.x, t = threadIdx.x;
    size_t base = (size_t)n * 512 + t * 4;
    float4 x = *(const float4*)&P[base];
    for (int s = 1; s < nsplit; s++) {
        float4 p = *(const float4*)&P[(size_t)s * (NTOK * DMODEL) + base];
        x.x += p.x; x.y += p.y; x.z += p.z; x.w += p.w;
    }
    {
        float4 bb4 = *(const float4*)&bias[t * 4];
        x.x += bb4.x; x.y += bb4.y; x.z += bb4.z; x.w += bb4.w;
        float4 r4 = *(const float4*)&res[base];
        x.x += r4.x; x.y += r4.y; x.z += r4.z; x.w += r4.w;
    }
    float s = x.x + x.y + x.z + x.w;
#pragma unroll
    for (int o = 16; o > 0; o >>= 1) s += __shfl_xor_sync(0xffffffffu, s, o);
    __shared__ float r1[4], r2[4];
    if ((t & 31) == 0) r1[t >> 5] = s;
    __syncthreads();
    float mean = (r1[0] + r1[1] + r1[2] + r1[3]) * (1.0f / 512.0f);
    float d0 = x.x - mean, d1 = x.y - mean, d2 = x.z - mean, d3 = x.w - mean;
    float ss = d0 * d0 + d1 * d1 + d2 * d2 + d3 * d3;
#pragma unroll
    for (int o = 16; o > 0; o >>= 1) ss += __shfl_xor_sync(0xffffffffu, ss, o);
    if ((t & 31) == 0) r2[t >> 5] = ss;
    __syncthreads();
    float var = (r2[0] + r2[1] + r2[2] + r2[3]) * (1.0f / 511.0f);
    float rstd = rsqrtf(var);
    float4 gg = *(const float4*)&g[base];
    float4 bb = *(const float4*)&be[base];
    float4 o4;
    o4.x = fmaf(gg.x * rstd, d0, bb.x);
    o4.y = fmaf(gg.y * rstd, d1, bb.y);
    o4.z = fmaf(gg.z * rstd, d2, bb.z);
    o4.w = fmaf(gg.w * rstd, d3, bb.w);
    *(float4*)&out[base] = o4;
}

// ---------------- orchestration ----------------
extern "C" void kernel_launch(void* const* d_in, const int* in_sizes, int n_in,
                              void* d_out, int out_size) {
    const int* ids = (const int*)d_in[0];
    const float* E = (const float*)d_in[1];
    const float* WQ = (const float*)d_in[2];
    const float* WK = (const float*)d_in[3];
    const float* WV = (const float*)d_in[4];
    const float* WO = (const float*)d_in[5];
    const float* ln1g = (const float*)d_in[6];
    const float* ln1b = (const float*)d_in[7];
    const float* W1 = (const float*)d_in[8];
    const float* b1 = (const float*)d_in[9];
    const float* W2 = (const float*)d_in[10];
    const float* b2 = (const float*)d_in[11];
    const float* ln2g = (const float*)d_in[12];
    const float* ln2b = (const float*)d_in[13];
    float* out = (float*)d_out;
    (void)in_sizes; (void)n_in; (void)out_size;

    float *X, *QKV, *corr, *bvec, *KVp, *Wc, *Z, *F, *P;
    float2* part;
    cudaGetSymbolAddress((void**)&X, g_X);
    cudaGetSymbolAddress((void**)&QKV, g_QKV);
    cudaGetSymbolAddress((void**)&part, g_part);
    cudaGetSymbolAddress((void**)&corr, g_corr);
    cudaGetSymbolAddress((void**)&bvec, g_bvec);
    cudaGetSymbolAddress((void**)&KVp, g_KVp);
    cudaGetSymbolAddress((void**)&Wc, g_Wc);
    cudaGetSymbolAddress((void**)&Z, g_Z);
    cudaGetSymbolAddress((void**)&F, g_F);
    cudaGetSymbolAddress((void**)&P, g_P);
    float* Q = QKV;
    float* Kb = QKV + NTOK * DMODEL;
    float* Vb = QKV + 2 * NTOK * DMODEL;

    embed_pe<<<NTOK, 128>>>(ids, E, X);

    for (int l = 0; l < NLAYER; l++) {
        const float* WQl = WQ + (size_t)l * NH * DMODEL * DHEAD;
        const float* WKl = WK + (size_t)l * NH * DMODEL * DHEAD;
        const float* WVl = WV + (size_t)l * NH * DMODEL * DHEAD;
        const float* WOl = WO + (size_t)l * DMODEL * DMODEL;
        const float* W1l = W1 + (size_t)l * DMODEL * DFFN;
        const float* b1l = b1 + (size_t)l * DFFN;
        const float* W2l = W2 + (size_t)l * DFFN * DMODEL;
        const float* b2l = b2 + (size_t)l * DMODEL;
        size_t lnOff = (size_t)l * NTOK * DMODEL;

        // ---- fused QKV projections: bz = op*8 + head ----
        gemm_tc<false, true, false><<<dim3(1, 16, 24), 256>>>(
            X, WQl, QKV, DMODEL, DMODEL, DHEAD, DMODEL,
            0LL, (long long)DMODEL * DHEAD, 0LL,
            nullptr, 0, nullptr, 0, 0LL, 1.0f, WKl, WVl, nullptr, 1, 1);

        // ---- fused QK^T/8 + column-lse partials (bf16, no S materialization) ----
        qk_lse<<<dim3(32, 16, 8), 256>>>(Q, Kb, part);

        // ---- K^T V partials (rank-2048 update, FMA; 256 blocks) ----
        ktv_kernel<<<dim3(32, 8), 256>>>(Kb, Vb, KVp);

        // ---- corr = -lse^T V ----
        lse_corr_kernel<<<NH, 256>>>(part, Vb, corr);

        // ---- Wc = blockdiag(G) WO (G reduced in-kernel), bvec = corr WO ----
        gwo_kernel<<<dim3(9, 8), 256>>>(KVp, WOl, Wc, corr, bvec);

        // ---- Z = LN1(Q Wc + bvec + X) (split-K x2, fused reduce+LN) ----
        gemm_tc<false, false, true><<<dim3(8, 16, 2), 256>>>(
            Q, Wc, nullptr, DMODEL, DMODEL, DMODEL, 0,
            0LL, 0LL, 0LL,
            nullptr, 0, nullptr, 0, 0LL, 1.0f, nullptr, nullptr, P, 2, 1);
        reduce_ln<<<NTOK, 128>>>(P, 2, bvec, X, ln1g + lnOff, ln1b + lnOff, Z);

        // ---- F = relu(Z @ W1 + b1) ----
        gemm_tc<true, false, false><<<dim3(32, 16, 1), 256>>>(
            Z, W1l, F, DMODEL, DMODEL, DFFN, DFFN,
            0LL, 0LL, 0LL,
            b1l, 0, nullptr, 0, 0LL, 1.0f, nullptr, nullptr, nullptr, 1, 1);

        // ---- X = LN2(F @ W2 + b2 + Z) (split-K x4, fused reduce+LN) ----
        gemm_tc<false, false, true><<<dim3(8, 16, 4), 256>>>(
            F, W2l, nullptr, DFFN, DFFN, DMODEL, 0,
            0LL, 0LL, 0LL,
            nullptr, 0, nullptr, 0, 0LL, 1.0f, nullptr, nullptr, P, 4, 1);
        reduce_ln<<<NTOK, 128>>>(P, 4, b2l, Z, ln2g + lnOff, ln2b + lnOff,
                                 (l == NLAYER - 1) ? out : X);
    }
}

// round 16
// speedup vs baseline: 1.1570x; 1.1570x over previous
#include <cuda_runtime.h>
#include <cstdint>

#define NTOK   2048
#define DMODEL 512
#define DFFN   2048
#define NH     8
#define DHEAD  64
#define NLAYER 6

// ---------------- device scratch (static, no allocation) ----------------
__device__ float g_X[NTOK * DMODEL];
__device__ float g_QKV[3 * NTOK * DMODEL];               // Q | K | V planes
__device__ float2 g_part[NH * 16 * NTOK];                // lse partials (2 MB)
__device__ float g_corr[NH * DHEAD];
__device__ float g_bvec[DMODEL];                         // corr @ WO
__device__ float g_KVp[NH * 32 * DHEAD * DHEAD];         // K^T V partials (4 MB)
__device__ float g_G[NH * DHEAD * DHEAD];                // K^T V / 8 per head
__device__ float g_Wc[DMODEL * DMODEL];                  // blockdiag(G) @ WO (1 MB)
__device__ float g_Z[NTOK * DMODEL];
__device__ float g_F[NTOK * DFFN];
__device__ float g_P[4 * NTOK * DMODEL];                 // split-K partials (16 MB)

// ---------------- fast exp (FMA-only, no MUFU) ----------------
__device__ __forceinline__ float fexp(float x) {
    x = fmaxf(x, -87.0f);
    float t = x * 1.4426950408889634f;
    const float big = 12582912.0f;
    float r = __fadd_rn(t, big) - big;
    float f = t - r;
    float p = 1.5403530e-4f;
    p = fmaf(p, f, 1.33335581e-3f);
    p = fmaf(p, f, 9.61812911e-3f);
    p = fmaf(p, f, 5.55041087e-2f);
    p = fmaf(p, f, 2.40226507e-1f);
    p = fmaf(p, f, 6.93147181e-1f);
    p = fmaf(p, f, 1.0f);
    int e = (int)r;
    return p * __int_as_float((e + 127) << 23);
}

// ---------------- bf16 / mma helpers ----------------
__device__ __forceinline__ uint32_t packbf(float e0, float e1) {  // e0 -> bits[15:0]
    uint32_t r;
    asm("cvt.rn.bf16x2.f32 %0, %1, %2;" : "=r"(r) : "f"(e1), "f"(e0));
    return r;
}
__device__ __forceinline__ float lo_f(uint32_t p) { return __uint_as_float(p << 16); }
__device__ __forceinline__ float hi_f(uint32_t p) { return __uint_as_float(p & 0xffff0000u); }

__device__ __forceinline__ void cvt_store4(char* hiP, char* loP, float4 v) {
    uint32_t h01 = packbf(v.x, v.y), h23 = packbf(v.z, v.w);
    uint32_t l01 = packbf(v.x - lo_f(h01), v.y - hi_f(h01));
    uint32_t l23 = packbf(v.z - lo_f(h23), v.w - hi_f(h23));
    *(uint2*)hiP = make_uint2(h01, h23);
    *(uint2*)loP = make_uint2(l01, l23);
}

__device__ __forceinline__ void ldsm4(uint32_t r[4], uint32_t addr) {
    asm volatile("ldmatrix.sync.aligned.m8n8.x4.shared.b16 {%0,%1,%2,%3}, [%4];"
                 : "=r"(r[0]), "=r"(r[1]), "=r"(r[2]), "=r"(r[3]) : "r"(addr));
}
__device__ __forceinline__ void ldsm4t(uint32_t r[4], uint32_t addr) {
    asm volatile("ldmatrix.sync.aligned.m8n8.x4.trans.shared.b16 {%0,%1,%2,%3}, [%4];"
                 : "=r"(r[0]), "=r"(r[1]), "=r"(r[2]), "=r"(r[3]) : "r"(addr));
}
__device__ __forceinline__ void mma_bf16(float d[4], const uint32_t a[4],
                                         uint32_t b0, uint32_t b1) {
    asm volatile(
        "mma.sync.aligned.m16n8k16.row.col.f32.bf16.bf16.f32 "
        "{%0,%1,%2,%3}, {%4,%5,%6,%7}, {%8,%9}, {%0,%1,%2,%3};"
        : "+f"(d[0]), "+f"(d[1]), "+f"(d[2]), "+f"(d[3])
        : "r"(a[0]), "r"(a[1]), "r"(a[2]), "r"(a[3]), "r"(b0), "r"(b1));
}

// ---------------- embedding + positional encoding ----------------
__global__ void embed_pe(const int* __restrict__ ids, const float* __restrict__ E,
                         float* __restrict__ X) {
    int n = blockIdx.x, t = threadIdx.x;                  // 128 threads
    int id = ids[n];
    float4 e = *(const float4*)&E[(size_t)id * DMODEL + t * 4];
    float ev[4] = {e.x, e.y, e.z, e.w};
    float pos = (float)(n + 1);
    float ov[4];
#pragma unroll
    for (int i = 0; i < 4; i++) {
        int d = t * 4 + i;
        int de = d & ~1;
        float f = expf((float)de * (-9.210340371976184f / 512.0f));
        float arg = pos * f;
        float pe = (d & 1) ? cosf(arg) : sinf(arg);
        ov[i] = ev[i] + pe;
    }
    *(float4*)&X[(size_t)n * DMODEL + t * 4] = *(float4*)ov;
}

// ---------------- bf16x3 tensor-core GEMM (champion single-buffer mainloop) ----------------
// NN only. C = alpha*A*B + bias + res, optional relu; or raw partials (split-K).
// BM=128, BN=64, BK=32; 256 threads / 8 warps; warp tile 32x32.
template <bool RELU, bool QKV, bool SPLITK>
__global__ void __launch_bounds__(256, 2)
gemm_tc(const float* __restrict__ Ag, const float* __restrict__ Bg,
        float* __restrict__ Cg, int K, int lda, int ldb, int ldc,
        long long sA, long long sB, long long sC,
        const float* __restrict__ biasg, int sBias,
        const float* __restrict__ resg, int ldr, long long sR,
        float alpha,
        const float* __restrict__ Bg1, const float* __restrict__ Bg2,
        float* __restrict__ Pbuf, int nsplit, int zInner) {
    __shared__ __align__(16) char sm[20480 + 8192];       // A hi/lo 2x10240, B hi/lo 2x4096
    char* Ahi = sm;
    char* Alo = sm + 10240;
    char* Bhi = sm + 20480;
    char* Blo = sm + 20480 + 4096;

    const int tid = threadIdx.x;
    const int bz = blockIdx.z;
    int bzIn = bz, split = 0;
    if (SPLITK) { bzIn = bz % zInner; split = bz / zInner; }
    const int kLen = SPLITK ? K / nsplit : K;
    const int kStart = SPLITK ? split * kLen : 0;

    const float* A = Ag + (size_t)bzIn * sA + (size_t)blockIdx.y * 128 * lda + kStart;
    const float* B;
    if (QKV) {
        int op = bz >> 3;
        const float* Bsel = (op == 0) ? Bg : (op == 1 ? Bg1 : Bg2);
        B = Bsel + (size_t)(bz & 7) * sB;
    } else {
        B = Bg + (size_t)bzIn * sB + (size_t)kStart * ldb + (size_t)blockIdx.x * 64;
    }

    const int ar = tid >> 3, ac = tid & 7;                // A loader coords
    const int kk_ld = tid >> 4, nb4 = (tid & 15) * 4;     // B loader coords

    float4 aR[4], bR[2];

    auto ldgA = [&](int k0) {
#pragma unroll
        for (int i = 0; i < 4; i++)
            aR[i] = *(const float4*)&A[(size_t)(ar + i * 32) * lda + k0 + ac * 4];
    };
    auto ldgB = [&](int k0) {
#pragma unroll
        for (int i = 0; i < 2; i++)
            bR[i] = *(const float4*)&B[(size_t)(k0 + kk_ld + i * 16) * ldb + nb4];
    };
    auto stsA = [&]() {
#pragma unroll
        for (int i = 0; i < 4; i++) {
            int off = (ar + i * 32) * 80 + ac * 8;        // 80B-pitch rows
            cvt_store4(Ahi + off, Alo + off, aR[i]);
        }
    };
    auto stsB = [&]() {
#pragma unroll
        for (int i = 0; i < 2; i++) {
            int k = kk_ld + i * 16;                       // [k][n] 128B rows, swizzled
            int off = k * 128 + (((nb4 >> 3) ^ (k & 7)) << 4) + ((nb4 & 4) << 1);
            cvt_store4(Bhi + off, Blo + off, bR[i]);
        }
    };

    const int lane = tid & 31, warp = tid >> 5;
    const int wm = (warp & 3) << 5, wn = (warp >> 2) << 5;
    uint32_t sm_u = (uint32_t)__cvta_generic_to_shared(sm);
    const uint32_t aBase = sm_u + (uint32_t)((wm + (lane & 15)) * 80 + (lane >> 4) * 16);
    const int krowL = (lane & 7) + ((lane >> 4) << 3);
    const int chnkL = (wn >> 3) + ((lane >> 3) & 1);

    float d[2][4][4];
#pragma unroll
    for (int i = 0; i < 2; i++)
#pragma unroll
        for (int j = 0; j < 4; j++)
#pragma unroll
            for (int q = 0; q < 4; q++) d[i][j][q] = 0.f;

    ldgA(0); ldgB(0);
    stsA(); stsB();
    __syncthreads();

    const int nkt = kLen >> 5;
    for (int kt = 0; kt < nkt; kt++) {
        if (kt + 1 < nkt) { ldgA((kt + 1) << 5); ldgB((kt + 1) << 5); }
#pragma unroll
        for (int ks = 0; ks < 2; ks++) {
            uint32_t ah[2][4], al[2][4], bh[2][4], bl[2][4];
#pragma unroll
            for (int mb = 0; mb < 2; mb++) {
                uint32_t a = aBase + (uint32_t)(mb * 16 * 80 + ks * 32);
                ldsm4(ah[mb], a);
                ldsm4(al[mb], a + 10240u);
            }
#pragma unroll
            for (int g = 0; g < 2; g++) {
                int k = ks * 16 + krowL;
                uint32_t b = sm_u + 20480u +
                             (uint32_t)(k * 128 + (((chnkL + g * 2) ^ (k & 7)) << 4));
                ldsm4t(bh[g], b);
                ldsm4t(bl[g], b + 4096u);
            }
#pragma unroll
            for (int mb = 0; mb < 2; mb++)
#pragma unroll
                for (int nb = 0; nb < 4; nb++) {
                    int g = nb >> 1, j = nb & 1;
                    uint32_t B0 = bh[g][j], B1 = bh[g][j + 2];
                    mma_bf16(d[mb][nb], ah[mb], B0, B1);
                    mma_bf16(d[mb][nb], ah[mb], bl[g][j], bl[g][j + 2]);
                    mma_bf16(d[mb][nb], al[mb], B0, B1);
                }
        }
        __syncthreads();
        if (kt + 1 < nkt) { stsA(); stsB(); __syncthreads(); }
    }

    const int gr = lane >> 2, gc = (lane & 3) * 2;
    const int mBase = blockIdx.y * 128 + wm;
    const int nBase = blockIdx.x * 64 + wn;
    if (SPLITK) {
        const int Mfull = gridDim.y * 128, Nfull = gridDim.x * 64;
        float* P = Pbuf + (size_t)(split * zInner + bzIn) * Mfull * Nfull;
#pragma unroll
        for (int mb = 0; mb < 2; mb++)
#pragma unroll
            for (int nb = 0; nb < 4; nb++)
#pragma unroll
                for (int h2 = 0; h2 < 2; h2++) {
                    int m = mBase + mb * 16 + gr + h2 * 8;
                    int n = nBase + nb * 8 + gc;
                    *(float2*)&P[(size_t)m * Nfull + n] =
                        make_float2(d[mb][nb][h2 * 2] * alpha, d[mb][nb][h2 * 2 + 1] * alpha);
                }
        return;
    }
    float* C;
    if (QKV) {
        C = Cg + (size_t)(bz >> 3) * (NTOK * DMODEL) + (size_t)(bz & 7) * 64;
    } else {
        C = Cg + (size_t)bzIn * sC;
    }
    const float* bi = biasg ? biasg + (size_t)bzIn * sBias : nullptr;
    const float* Rg = resg ? resg + (size_t)bzIn * sR : nullptr;
#pragma unroll
    for (int mb = 0; mb < 2; mb++)
#pragma unroll
        for (int nb = 0; nb < 4; nb++)
#pragma unroll
            for (int h2 = 0; h2 < 2; h2++) {
                int m = mBase + mb * 16 + gr + h2 * 8;
                int n = nBase + nb * 8 + gc;
                float v0 = d[mb][nb][h2 * 2] * alpha;
                float v1 = d[mb][nb][h2 * 2 + 1] * alpha;
                if (bi) {
                    float2 bb = *(const float2*)&bi[n];
                    v0 += bb.x; v1 += bb.y;
                }
                if (Rg) {
                    float2 rr = *(const float2*)&Rg[(size_t)m * ldr + n];
                    v0 += rr.x; v1 += rr.y;
                }
                if (RELU) { v0 = fmaxf(v0, 0.f); v1 = fmaxf(v1, 0.f); }
                *(float2*)&C[(size_t)m * ldc + n] = make_float2(v0, v1);
            }
}

// ---------------- fused QK^T tile + column (max, sumexp) partials (bf16 compute) --------
__global__ void __launch_bounds__(256, 2)
qk_lse(const float* __restrict__ Qg, const float* __restrict__ Kg,
       float2* __restrict__ part) {
    __shared__ __align__(16) char sm[128 * 144 + 64 * 144];   // A 18432B | B 9216B
    char* Asm = sm;
    char* Bsm = sm + 128 * 144;

    const int tid = threadIdx.x;
    const int h = blockIdx.z;
    const float* A = Qg + h * 64 + (size_t)blockIdx.y * 128 * DMODEL;
    const float* B = Kg + h * 64 + (size_t)blockIdx.x * 64 * DMODEL;

    // load + convert: A = 2048 float4, B = 1024 float4
#pragma unroll
    for (int r = 0; r < 8; r++) {
        int idx = tid + r * 256;                          // 0..2047
        int row = idx >> 4, c4 = (idx & 15) * 4;
        float4 v = *(const float4*)&A[(size_t)row * DMODEL + c4];
        *(uint2*)(Asm + row * 144 + c4 * 2) =
            make_uint2(packbf(v.x, v.y), packbf(v.z, v.w));
    }
#pragma unroll
    for (int r = 0; r < 4; r++) {
        int idx = tid + r * 256;                          // 0..1023
        int row = idx >> 4, c4 = (idx & 15) * 4;
        float4 v = *(const float4*)&B[(size_t)row * DMODEL + c4];
        *(uint2*)(Bsm + row * 144 + c4 * 2) =
            make_uint2(packbf(v.x, v.y), packbf(v.z, v.w));
    }
    __syncthreads();

    const int lane = tid & 31, warp = tid >> 5;
    const int wm = (warp & 3) << 5, wn = (warp >> 2) << 5;
    uint32_t sm_u = (uint32_t)__cvta_generic_to_shared(sm);
    const uint32_t aBase = sm_u + (uint32_t)((wm + (lane & 15)) * 144 + (lane >> 4) * 16);
    const uint32_t bBase = sm_u + (uint32_t)(128 * 144) +
                           (uint32_t)((wn + (lane & 15)) * 144 + (lane >> 4) * 16);

    float d[2][4][4];
#pragma unroll
    for (int i = 0; i < 2; i++)
#pragma unroll
        for (int j = 0; j < 4; j++)
#pragma unroll
            for (int q = 0; q < 4; q++) d[i][j][q] = 0.f;

#pragma unroll
    for (int ks = 0; ks < 4; ks++) {
        uint32_t ah[2][4], bh[2][4];
#pragma unroll
        for (int mb = 0; mb < 2; mb++)
            ldsm4(ah[mb], aBase + (uint32_t)(mb * 16 * 144 + ks * 32));
#pragma unroll
        for (int g = 0; g < 2; g++)
            ldsm4(bh[g], bBase + (uint32_t)(g * 16 * 144 + ks * 32));
#pragma unroll
        for (int mb = 0; mb < 2; mb++)
#pragma unroll
            for (int nb = 0; nb < 4; nb++) {
                int g = nb >> 1, j = nb & 1;
                mma_bf16(d[mb][nb], ah[mb], bh[g][j], bh[g][j + 2]);
            }
    }

    // ---- per-column (max, sumexp) over this block's 128 q-rows ----
    const int gc0 = (lane & 3) * 2;
    float cm[8], cs[8];
#pragma unroll
    for (int idx = 0; idx < 8; idx++) {
        int nb = idx >> 1, j = idx & 1;
        float v0 = d[0][nb][j] * 0.125f;
        float v1 = d[0][nb][2 + j] * 0.125f;
        float v2 = d[1][nb][j] * 0.125f;
        float v3 = d[1][nb][2 + j] * 0.125f;
        float m = fmaxf(fmaxf(v0, v1), fmaxf(v2, v3));
        cm[idx] = m;
        cs[idx] = fexp(v0 - m) + fexp(v1 - m) + fexp(v2 - m) + fexp(v3 - m);
    }
#pragma unroll
    for (int off = 4; off <= 16; off <<= 1) {
#pragma unroll
        for (int idx = 0; idx < 8; idx++) {
            float om = __shfl_xor_sync(0xffffffffu, cm[idx], off);
            float os = __shfl_xor_sync(0xffffffffu, cs[idx], off);
            float nm = fmaxf(cm[idx], om);
            cs[idx] = cs[idx] * fexp(cm[idx] - nm) + os * fexp(om - nm);
            cm[idx] = nm;
        }
    }
    __syncthreads();
    float2* psm = (float2*)sm;                            // [4][64], aliases mainloop smem
    if (lane < 4) {
#pragma unroll
        for (int idx = 0; idx < 8; idx++) {
            int nb = idx >> 1, j = idx & 1;
            int col = wn + gc0 + j + nb * 8;
            psm[(warp & 3) * 64 + col] = make_float2(cm[idx], cs[idx]);
        }
    }
    __syncthreads();
    if (tid < 64) {
        float2 a = psm[tid];
        float m = a.x, s = a.y;
#pragma unroll
        for (int w = 1; w < 4; w++) {
            float2 b = psm[w * 64 + tid];
            float nm = fmaxf(m, b.x);
            s = s * fexp(m - nm) + b.y * fexp(b.x - nm);
            m = nm;
        }
        part[((size_t)h * 16 + blockIdx.y) * NTOK + blockIdx.x * 64 + tid] =
            make_float2(m, s);
    }
}

// ---------------- fused lse-combine + corr: corr[h][v] = -sum_m lse[h,m] V[m,h64+v] ----
__global__ void lse_corr_kernel(const float2* __restrict__ part,
                                const float* __restrict__ Vb,
                                float* __restrict__ corr) {
    const int h = blockIdx.x, t = threadIdx.x;            // 256 threads
    __shared__ float slse[NTOK];
    __shared__ float red[256];
#pragma unroll
    for (int i = 0; i < 8; i++) {
        int m = t + 256 * i;
        float mx = -3.0e38f;
        float2 p[16];
#pragma unroll
        for (int s = 0; s < 16; s++) {
            p[s] = part[((size_t)h * 16 + s) * NTOK + m];
            mx = fmaxf(mx, p[s].x);
        }
        float sum = 0.f;
#pragma unroll
        for (int s = 0; s < 16; s++) sum += p[s].y * expf(p[s].x - mx);
        slse[m] = mx + logf(sum);
    }
    __syncthreads();
    int v = t & 63, seg = t >> 6;
    const float* Vp = Vb + h * 64 + v;
    float acc = 0.f;
    for (int m = seg * 512; m < seg * 512 + 512; m++)
        acc = fmaf(slse[m], Vp[(size_t)m * DMODEL], acc);
    red[t] = acc;
    __syncthreads();
    if (t < 64) {
        float tot = red[t] + red[t + 64] + red[t + 128] + red[t + 192];
        corr[h * 64 + t] = -tot;
    }
}

// ---------------- K^T V rank-update partials: per (head, m-chunk of 64) ----------------
__global__ void __launch_bounds__(256)
ktv_kernel(const float* __restrict__ Kg, const float* __restrict__ Vg,
           float* __restrict__ Pk) {
    const int chunk = blockIdx.x, h = blockIdx.y;         // 32 chunks x 8 heads
    const int tid = threadIdx.x;
    const int td = tid & 15, tv = tid >> 4;               // 16x16 thread grid, 4x4 tiles
    __shared__ float sk[32][64], sv[32][64];
    const float* Kp = Kg + h * 64;
    const float* Vp = Vg + h * 64;
    const int m0 = chunk * 64;

    float acc[4][4];
#pragma unroll
    for (int i = 0; i < 4; i++)
#pragma unroll
        for (int j = 0; j < 4; j++) acc[i][j] = 0.f;

    for (int mb = 0; mb < 64; mb += 32) {
        __syncthreads();
#pragma unroll
        for (int r = 0; r < 2; r++) {
            int i = tid + r * 256;                        // float4 index 0..511
            int mi = i >> 4, c4 = (i & 15) * 4;
            *(float4*)&sk[mi][c4] =
                *(const float4*)&Kp[(size_t)(m0 + mb + mi) * DMODEL + c4];
            *(float4*)&sv[mi][c4] =
                *(const float4*)&Vp[(size_t)(m0 + mb + mi) * DMODEL + c4];
        }
        __syncthreads();
#pragma unroll 8
        for (int mi = 0; mi < 32; mi++) {
            float4 kk = *(const float4*)&sk[mi][td * 4];
            float4 vv = *(const float4*)&sv[mi][tv * 4];
            float ka[4] = {kk.x, kk.y, kk.z, kk.w};
            float va[4] = {vv.x, vv.y, vv.z, vv.w};
#pragma unroll
            for (int i = 0; i < 4; i++)
#pragma unroll
                for (int j = 0; j < 4; j++)
                    acc[i][j] = fmaf(ka[i], va[j], acc[i][j]);
        }
    }
    float* P = Pk + ((size_t)h * 32 + chunk) * (DHEAD * DHEAD);
#pragma unroll
    for (int i = 0; i < 4; i++)
        *(float4*)&P[(td * 4 + i) * 64 + tv * 4] = *(float4*)acc[i];
}

// G[h] = 0.125 * sum over 32 chunks (parallel, 8192 threads)
__global__ void ktv_reduce(const float* __restrict__ Pk, float* __restrict__ G) {
    int idx = blockIdx.x * 256 + threadIdx.x;             // 8192 float4's
    int h = idx >> 10, e = (idx & 1023) * 4;
    const float* P = Pk + (size_t)h * 32 * (DHEAD * DHEAD) + e;
    float4 v = *(const float4*)P;
#pragma unroll
    for (int c = 1; c < 32; c++) {
        float4 p = *(const float4*)&P[c * DHEAD * DHEAD];
        v.x += p.x; v.y += p.y; v.z += p.z; v.w += p.w;
    }
    v.x *= 0.125f; v.y *= 0.125f; v.z *= 0.125f; v.w *= 0.125f;
    *(float4*)&G[(size_t)h * DHEAD * DHEAD + e] = v;
}

// ---------------- Wc = blockdiag(G) @ WO, plus bvec = corr @ WO (jt==8 branch) ----------
__global__ void __launch_bounds__(256)
gwo_kernel(const float* __restrict__ G, const float* __restrict__ WO,
           float* __restrict__ Wc, const float* __restrict__ corr,
           float* __restrict__ bvec) {
    const int jt = blockIdx.x, h = blockIdx.y;            // (9 x 8) blocks
    const int tid = threadIdx.x;
    __shared__ float sg[64][65];
    __shared__ float sw[64][68];

    if (jt == 8) {
        // bvec[h*64 + c] = sum_i corr[i] * WO[i][h*64 + c]
        float* red = &sg[0][0];
        int c = tid & 63, seg = tid >> 6;
        float acc = 0.f;
        for (int i = seg * 128; i < seg * 128 + 128; i++)
            acc = fmaf(corr[i], WO[(size_t)i * DMODEL + h * 64 + c], acc);
        red[tid] = acc;
        __syncthreads();
        if (tid < 64)
            bvec[h * 64 + tid] = red[tid] + red[tid + 64] + red[tid + 128] + red[tid + 192];
        return;
    }

    const int tj = tid & 15, td = tid >> 4;
#pragma unroll
    for (int r = 0; r < 16; r++) {
        int i = tid + r * 256;
        int row = i >> 6, c = i & 63;
        sg[row][c] = G[(size_t)h * 4096 + i];
        sw[row][c] = WO[(size_t)(h * 64 + row) * DMODEL + jt * 64 + c];
    }
    __syncthreads();
    float acc[4][4];
#pragma unroll
    for (int i = 0; i < 4; i++)
#pragma unroll
        for (int j = 0; j < 4; j++) acc[i][j] = 0.f;
#pragma unroll 8
    for (int v = 0; v < 64; v++) {
        float a[4], w[4];
#pragma unroll
        for (int i = 0; i < 4; i++) a[i] = sg[td * 4 + i][v];
        float4 w4 = *(const float4*)&sw[v][tj * 4];
        w[0] = w4.x; w[1] = w4.y; w[2] = w4.z; w[3] = w4.w;
#pragma unroll
        for (int i = 0; i < 4; i++)
#pragma unroll
            for (int j = 0; j < 4; j++)
                acc[i][j] = fmaf(a[i], w[j], acc[i][j]);
    }
#pragma unroll
    for (int i = 0; i < 4; i++)
        *(float4*)&Wc[(size_t)(h * 64 + td * 4 + i) * DMODEL + jt * 64 + tj * 4] =
            *(float4*)acc[i];
}

// ---------------- fused split-K reduce + bias + residual + layernorm ----------------
__global__ void __launch_bounds__(128)
reduce_ln(const float* __restrict__ P, int nsplit,
          const float* __restrict__ bias, const float* __restrict__ res,
          const float* __restrict__ g, const float* __restrict__ be,
          float* __restrict__ out) {
    int n = blockIdx.x, t = threadIdx.x;
    size_t base = (size_t)n * 512 + t * 4;
    float4 x = *(const float4*)&P[base];
    for (int s = 1; s < nsplit; s++) {
        float4 p = *(const float4*)&P[(size_t)s * (NTOK * DMODEL) + base];
        x.x += p.x; x.y += p.y; x.z += p.z; x.w += p.w;
    }
    {
        float4 bb4 = *(const float4*)&bias[t * 4];
        x.x += bb4.x; x.y += bb4.y; x.z += bb4.z; x.w += bb4.w;
        float4 r4 = *(const float4*)&res[base];
        x.x += r4.x; x.y += r4.y; x.z += r4.z; x.w += r4.w;
    }
    float s = x.x + x.y + x.z + x.w;
#pragma unroll
    for (int o = 16; o > 0; o >>= 1) s += __shfl_xor_sync(0xffffffffu, s, o);
    __shared__ float r1[4], r2[4];
    if ((t & 31) == 0) r1[t >> 5] = s;
    __syncthreads();
    float mean = (r1[0] + r1[1] + r1[2] + r1[3]) * (1.0f / 512.0f);
    float d0 = x.x - mean, d1 = x.y - mean, d2 = x.z - mean, d3 = x.w - mean;
    float ss = d0 * d0 + d1 * d1 + d2 * d2 + d3 * d3;
#pragma unroll
    for (int o = 16; o > 0; o >>= 1) ss += __shfl_xor_sync(0xffffffffu, ss, o);
    if ((t & 31) == 0) r2[t >> 5] = ss;
    __syncthreads();
    float var = (r2[0] + r2[1] + r2[2] + r2[3]) * (1.0f / 511.0f);
    float rstd = rsqrtf(var);
    float4 gg = *(const float4*)&g[base];
    float4 bb = *(const float4*)&be[base];
    float4 o4;
    o4.x = fmaf(gg.x * rstd, d0, bb.x);
    o4.y = fmaf(gg.y * rstd, d1, bb.y);
    o4.z = fmaf(gg.z * rstd, d2, bb.z);
    o4.w = fmaf(gg.w * rstd, d3, bb.w);
    *(float4*)&out[base] = o4;
}

// ---------------- orchestration ----------------
extern "C" void kernel_launch(void* const* d_in, const int* in_sizes, int n_in,
                              void* d_out, int out_size) {
    const int* ids = (const int*)d_in[0];
    const float* E = (const float*)d_in[1];
    const float* WQ = (const float*)d_in[2];
    const float* WK = (const float*)d_in[3];
    const float* WV = (const float*)d_in[4];
    const float* WO = (const float*)d_in[5];
    const float* ln1g = (const float*)d_in[6];
    const float* ln1b = (const float*)d_in[7];
    const float* W1 = (const float*)d_in[8];
    const float* b1 = (const float*)d_in[9];
    const float* W2 = (const float*)d_in[10];
    const float* b2 = (const float*)d_in[11];
    const float* ln2g = (const float*)d_in[12];
    const float* ln2b = (const float*)d_in[13];
    float* out = (float*)d_out;
    (void)in_sizes; (void)n_in; (void)out_size;

    float *X, *QKV, *corr, *bvec, *KVp, *G, *Wc, *Z, *F, *P;
    float2* part;
    cudaGetSymbolAddress((void**)&X, g_X);
    cudaGetSymbolAddress((void**)&QKV, g_QKV);
    cudaGetSymbolAddress((void**)&part, g_part);
    cudaGetSymbolAddress((void**)&corr, g_corr);
    cudaGetSymbolAddress((void**)&bvec, g_bvec);
    cudaGetSymbolAddress((void**)&KVp, g_KVp);
    cudaGetSymbolAddress((void**)&G, g_G);
    cudaGetSymbolAddress((void**)&Wc, g_Wc);
    cudaGetSymbolAddress((void**)&Z, g_Z);
    cudaGetSymbolAddress((void**)&F, g_F);
    cudaGetSymbolAddress((void**)&P, g_P);
    float* Q = QKV;
    float* Kb = QKV + NTOK * DMODEL;
    float* Vb = QKV + 2 * NTOK * DMODEL;

    embed_pe<<<NTOK, 128>>>(ids, E, X);

    for (int l = 0; l < NLAYER; l++) {
        const float* WQl = WQ + (size_t)l * NH * DMODEL * DHEAD;
        const float* WKl = WK + (size_t)l * NH * DMODEL * DHEAD;
        const float* WVl = WV + (size_t)l * NH * DMODEL * DHEAD;
        const float* WOl = WO + (size_t)l * DMODEL * DMODEL;
        const float* W1l = W1 + (size_t)l * DMODEL * DFFN;
        const float* b1l = b1 + (size_t)l * DFFN;
        const float* W2l = W2 + (size_t)l * DFFN * DMODEL;
        const float* b2l = b2 + (size_t)l * DMODEL;
        size_t lnOff = (size_t)l * NTOK * DMODEL;

        // ---- fused QKV projections: bz = op*8 + head ----
        gemm_tc<false, true, false><<<dim3(1, 16, 24), 256>>>(
            X, WQl, QKV, DMODEL, DMODEL, DHEAD, DMODEL,
            0LL, (long long)DMODEL * DHEAD, 0LL,
            nullptr, 0, nullptr, 0, 0LL, 1.0f, WKl, WVl, nullptr, 1, 1);

        // ---- fused QK^T/8 + column-lse partials (bf16, no S materialization) ----
        qk_lse<<<dim3(32, 16, 8), 256>>>(Q, Kb, part);

        // ---- G_h = K_h^T V_h / 8 (rank-2048 update, FMA; 256 blocks) ----
        ktv_kernel<<<dim3(32, 8), 256>>>(Kb, Vb, KVp);
        ktv_reduce<<<32, 256>>>(KVp, G);

        // ---- corr = -lse^T V ----
        lse_corr_kernel<<<NH, 256>>>(part, Vb, corr);

        // ---- Wc = blockdiag(G) WO and bvec = corr WO, one launch ----
        gwo_kernel<<<dim3(9, 8), 256>>>(G, WOl, Wc, corr, bvec);

        // ---- Z = LN1(Q Wc + bvec + X) (split-K x2, fused reduce+LN) ----
        gemm_tc<false, false, true><<<dim3(8, 16, 2), 256>>>(
            Q, Wc, nullptr, DMODEL, DMODEL, DMODEL, 0,
            0LL, 0LL, 0LL,
            nullptr, 0, nullptr, 0, 0LL, 1.0f, nullptr, nullptr, P, 2, 1);
        reduce_ln<<<NTOK, 128>>>(P, 2, bvec, X, ln1g + lnOff, ln1b + lnOff, Z);

        // ---- F = relu(Z @ W1 + b1) ----
        gemm_tc<true, false, false><<<dim3(32, 16, 1), 256>>>(
            Z, W1l, F, DMODEL, DMODEL, DFFN, DFFN,
            0LL, 0LL, 0LL,
            b1l, 0, nullptr, 0, 0LL, 1.0f, nullptr, nullptr, nullptr, 1, 1);

        // ---- X = LN2(F @ W2 + b2 + Z) (split-K x2, fused reduce+LN) ----
        gemm_tc<false, false, true><<<dim3(8, 16, 2), 256>>>(
            F, W2l, nullptr, DFFN, DFFN, DMODEL, 0,
            0LL, 0LL, 0LL,
            nullptr, 0, nullptr, 0, 0LL, 1.0f, nullptr, nullptr, P, 2, 1);
        reduce_ln<<<NTOK, 128>>>(P, 2, b2l, Z, ln2g + lnOff, ln2b + lnOff,
                                 (l == NLAYER - 1) ? out : X);
    }
}

// round 17
// speedup vs baseline: 1.1820x; 1.0216x over previous
#include <cuda_runtime.h>
#include <cstdint>

#define NTOK   2048
#define DMODEL 512
#define DFFN   2048
#define NH     8
#define DHEAD  64
#define NLAYER 6

// ---------------- device scratch (static, no allocation) ----------------
__device__ float g_X[NTOK * DMODEL];
__device__ float g_QKV[3 * NTOK * DMODEL];               // Q | K | V planes
__device__ float2 g_part[NH * 16 * NTOK];                // lse partials (2 MB)
__device__ float g_corr[NH * DHEAD];
__device__ float g_bvec[DMODEL];                         // corr @ WO
__device__ float g_KVp[NH * 32 * DHEAD * DHEAD];         // K^T V partials (4 MB)
__device__ float g_G[NH * DHEAD * DHEAD];                // K^T V / 8 per head
__device__ float g_Wc[DMODEL * DMODEL];                  // blockdiag(G) @ WO (1 MB)
__device__ float g_Z[NTOK * DMODEL];
__device__ float g_F[NTOK * DFFN];
__device__ float g_P[4 * NTOK * DMODEL];                 // split-K partials (16 MB)

// ---------------- fast exp (FMA-only, no MUFU) ----------------
__device__ __forceinline__ float fexp(float x) {
    x = fmaxf(x, -87.0f);
    float t = x * 1.4426950408889634f;
    const float big = 12582912.0f;
    float r = __fadd_rn(t, big) - big;
    float f = t - r;
    float p = 1.5403530e-4f;
    p = fmaf(p, f, 1.33335581e-3f);
    p = fmaf(p, f, 9.61812911e-3f);
    p = fmaf(p, f, 5.55041087e-2f);
    p = fmaf(p, f, 2.40226507e-1f);
    p = fmaf(p, f, 6.93147181e-1f);
    p = fmaf(p, f, 1.0f);
    int e = (int)r;
    return p * __int_as_float((e + 127) << 23);
}

// ---------------- bf16 / mma helpers ----------------
__device__ __forceinline__ uint32_t packbf(float e0, float e1) {  // e0 -> bits[15:0]
    uint32_t r;
    asm("cvt.rn.bf16x2.f32 %0, %1, %2;" : "=r"(r) : "f"(e1), "f"(e0));
    return r;
}
__device__ __forceinline__ float lo_f(uint32_t p) { return __uint_as_float(p << 16); }
__device__ __forceinline__ float hi_f(uint32_t p) { return __uint_as_float(p & 0xffff0000u); }

__device__ __forceinline__ void cvt_store4(char* hiP, char* loP, float4 v) {
    uint32_t h01 = packbf(v.x, v.y), h23 = packbf(v.z, v.w);
    uint32_t l01 = packbf(v.x - lo_f(h01), v.y - hi_f(h01));
    uint32_t l23 = packbf(v.z - lo_f(h23), v.w - hi_f(h23));
    *(uint2*)hiP = make_uint2(h01, h23);
    *(uint2*)loP = make_uint2(l01, l23);
}

__device__ __forceinline__ void ldsm4(uint32_t r[4], uint32_t addr) {
    asm volatile("ldmatrix.sync.aligned.m8n8.x4.shared.b16 {%0,%1,%2,%3}, [%4];"
                 : "=r"(r[0]), "=r"(r[1]), "=r"(r[2]), "=r"(r[3]) : "r"(addr));
}
__device__ __forceinline__ void ldsm4t(uint32_t r[4], uint32_t addr) {
    asm volatile("ldmatrix.sync.aligned.m8n8.x4.trans.shared.b16 {%0,%1,%2,%3}, [%4];"
                 : "=r"(r[0]), "=r"(r[1]), "=r"(r[2]), "=r"(r[3]) : "r"(addr));
}
__device__ __forceinline__ void mma_bf16(float d[4], const uint32_t a[4],
                                         uint32_t b0, uint32_t b1) {
    asm volatile(
        "mma.sync.aligned.m16n8k16.row.col.f32.bf16.bf16.f32 "
        "{%0,%1,%2,%3}, {%4,%5,%6,%7}, {%8,%9}, {%0,%1,%2,%3};"
        : "+f"(d[0]), "+f"(d[1]), "+f"(d[2]), "+f"(d[3])
        : "r"(a[0]), "r"(a[1]), "r"(a[2]), "r"(a[3]), "r"(b0), "r"(b1));
}

// ---------------- embedding + positional encoding ----------------
__global__ void embed_pe(const int* __restrict__ ids, const float* __restrict__ E,
                         float* __restrict__ X) {
    int n = blockIdx.x, t = threadIdx.x;                  // 128 threads
    int id = ids[n];
    float4 e = *(const float4*)&E[(size_t)id * DMODEL + t * 4];
    float ev[4] = {e.x, e.y, e.z, e.w};
    float pos = (float)(n + 1);
    float ov[4];
#pragma unroll
    for (int i = 0; i < 4; i++) {
        int d = t * 4 + i;
        int de = d & ~1;
        float f = expf((float)de * (-9.210340371976184f / 512.0f));
        float arg = pos * f;
        float pe = (d & 1) ? cosf(arg) : sinf(arg);
        ov[i] = ev[i] + pe;
    }
    *(float4*)&X[(size_t)n * DMODEL + t * 4] = *(float4*)ov;
}

// ---------------- bf16x3 tensor-core GEMM (champion single-buffer mainloop) ----------------
// NN only. C = alpha*A*B + bias + res, optional relu; or raw partials (split-K).
// BM=128, BN=64, BK=32; 256 threads / 8 warps; warp tile 32x32.
template <bool RELU, bool QKV, bool SPLITK>
__global__ void __launch_bounds__(256, 2)
gemm_tc(const float* __restrict__ Ag, const float* __restrict__ Bg,
        float* __restrict__ Cg, int K, int lda, int ldb, int ldc,
        long long sA, long long sB, long long sC,
        const float* __restrict__ biasg, int sBias,
        const float* __restrict__ resg, int ldr, long long sR,
        float alpha,
        const float* __restrict__ Bg1, const float* __restrict__ Bg2,
        float* __restrict__ Pbuf, int nsplit, int zInner) {
    __shared__ __align__(16) char sm[20480 + 8192];       // A hi/lo 2x10240, B hi/lo 2x4096
    char* Ahi = sm;
    char* Alo = sm + 10240;
    char* Bhi = sm + 20480;
    char* Blo = sm + 20480 + 4096;

    const int tid = threadIdx.x;
    const int bz = blockIdx.z;
    int bzIn = bz, split = 0;
    if (SPLITK) { bzIn = bz % zInner; split = bz / zInner; }
    const int kLen = SPLITK ? K / nsplit : K;
    const int kStart = SPLITK ? split * kLen : 0;

    const float* A = Ag + (size_t)bzIn * sA + (size_t)blockIdx.y * 128 * lda + kStart;
    const float* B;
    if (QKV) {
        int op = bz >> 3;
        const float* Bsel = (op == 0) ? Bg : (op == 1 ? Bg1 : Bg2);
        B = Bsel + (size_t)(bz & 7) * sB;
    } else {
        B = Bg + (size_t)bzIn * sB + (size_t)kStart * ldb + (size_t)blockIdx.x * 64;
    }

    const int ar = tid >> 3, ac = tid & 7;                // A loader coords
    const int kk_ld = tid >> 4, nb4 = (tid & 15) * 4;     // B loader coords

    float4 aR[4], bR[2];

    auto ldgA = [&](int k0) {
#pragma unroll
        for (int i = 0; i < 4; i++)
            aR[i] = *(const float4*)&A[(size_t)(ar + i * 32) * lda + k0 + ac * 4];
    };
    auto ldgB = [&](int k0) {
#pragma unroll
        for (int i = 0; i < 2; i++)
            bR[i] = *(const float4*)&B[(size_t)(k0 + kk_ld + i * 16) * ldb + nb4];
    };
    auto stsA = [&]() {
#pragma unroll
        for (int i = 0; i < 4; i++) {
            int off = (ar + i * 32) * 80 + ac * 8;        // 80B-pitch rows
            cvt_store4(Ahi + off, Alo + off, aR[i]);
        }
    };
    auto stsB = [&]() {
#pragma unroll
        for (int i = 0; i < 2; i++) {
            int k = kk_ld + i * 16;                       // [k][n] 128B rows, swizzled
            int off = k * 128 + (((nb4 >> 3) ^ (k & 7)) << 4) + ((nb4 & 4) << 1);
            cvt_store4(Bhi + off, Blo + off, bR[i]);
        }
    };

    const int lane = tid & 31, warp = tid >> 5;
    const int wm = (warp & 3) << 5, wn = (warp >> 2) << 5;
    uint32_t sm_u = (uint32_t)__cvta_generic_to_shared(sm);
    const uint32_t aBase = sm_u + (uint32_t)((wm + (lane & 15)) * 80 + (lane >> 4) * 16);
    const int krowL = (lane & 7) + ((lane >> 4) << 3);
    const int chnkL = (wn >> 3) + ((lane >> 3) & 1);

    float d[2][4][4];
#pragma unroll
    for (int i = 0; i < 2; i++)
#pragma unroll
        for (int j = 0; j < 4; j++)
#pragma unroll
            for (int q = 0; q < 4; q++) d[i][j][q] = 0.f;

    ldgA(0); ldgB(0);
    stsA(); stsB();
    __syncthreads();

    const int nkt = kLen >> 5;
    for (int kt = 0; kt < nkt; kt++) {
        if (kt + 1 < nkt) { ldgA((kt + 1) << 5); ldgB((kt + 1) << 5); }
#pragma unroll
        for (int ks = 0; ks < 2; ks++) {
            uint32_t ah[2][4], al[2][4], bh[2][4], bl[2][4];
#pragma unroll
            for (int mb = 0; mb < 2; mb++) {
                uint32_t a = aBase + (uint32_t)(mb * 16 * 80 + ks * 32);
                ldsm4(ah[mb], a);
                ldsm4(al[mb], a + 10240u);
            }
#pragma unroll
            for (int g = 0; g < 2; g++) {
                int k = ks * 16 + krowL;
                uint32_t b = sm_u + 20480u +
                             (uint32_t)(k * 128 + (((chnkL + g * 2) ^ (k & 7)) << 4));
                ldsm4t(bh[g], b);
                ldsm4t(bl[g], b + 4096u);
            }
#pragma unroll
            for (int mb = 0; mb < 2; mb++)
#pragma unroll
                for (int nb = 0; nb < 4; nb++) {
                    int g = nb >> 1, j = nb & 1;
                    uint32_t B0 = bh[g][j], B1 = bh[g][j + 2];
                    mma_bf16(d[mb][nb], ah[mb], B0, B1);
                    mma_bf16(d[mb][nb], ah[mb], bl[g][j], bl[g][j + 2]);
                    mma_bf16(d[mb][nb], al[mb], B0, B1);
                }
        }
        __syncthreads();
        if (kt + 1 < nkt) { stsA(); stsB(); __syncthreads(); }
    }

    const int gr = lane >> 2, gc = (lane & 3) * 2;
    const int mBase = blockIdx.y * 128 + wm;
    const int nBase = blockIdx.x * 64 + wn;
    if (SPLITK) {
        const int Mfull = gridDim.y * 128, Nfull = gridDim.x * 64;
        float* P = Pbuf + (size_t)(split * zInner + bzIn) * Mfull * Nfull;
#pragma unroll
        for (int mb = 0; mb < 2; mb++)
#pragma unroll
            for (int nb = 0; nb < 4; nb++)
#pragma unroll
                for (int h2 = 0; h2 < 2; h2++) {
                    int m = mBase + mb * 16 + gr + h2 * 8;
                    int n = nBase + nb * 8 + gc;
                    *(float2*)&P[(size_t)m * Nfull + n] =
                        make_float2(d[mb][nb][h2 * 2] * alpha, d[mb][nb][h2 * 2 + 1] * alpha);
                }
        return;
    }
    float* C;
    if (QKV) {
        C = Cg + (size_t)(bz >> 3) * (NTOK * DMODEL) + (size_t)(bz & 7) * 64;
    } else {
        C = Cg + (size_t)bzIn * sC;
    }
    const float* bi = biasg ? biasg + (size_t)bzIn * sBias : nullptr;
    const float* Rg = resg ? resg + (size_t)bzIn * sR : nullptr;
#pragma unroll
    for (int mb = 0; mb < 2; mb++)
#pragma unroll
        for (int nb = 0; nb < 4; nb++)
#pragma unroll
            for (int h2 = 0; h2 < 2; h2++) {
                int m = mBase + mb * 16 + gr + h2 * 8;
                int n = nBase + nb * 8 + gc;
                float v0 = d[mb][nb][h2 * 2] * alpha;
                float v1 = d[mb][nb][h2 * 2 + 1] * alpha;
                if (bi) {
                    float2 bb = *(const float2*)&bi[n];
                    v0 += bb.x; v1 += bb.y;
                }
                if (Rg) {
                    float2 rr = *(const float2*)&Rg[(size_t)m * ldr + n];
                    v0 += rr.x; v1 += rr.y;
                }
                if (RELU) { v0 = fmaxf(v0, 0.f); v1 = fmaxf(v1, 0.f); }
                *(float2*)&C[(size_t)m * ldc + n] = make_float2(v0, v1);
            }
}

// ---------------- fused QK^T tile + column (max, sumexp) partials (bf16 compute) --------
__global__ void __launch_bounds__(256, 2)
qk_lse(const float* __restrict__ Qg, const float* __restrict__ Kg,
       float2* __restrict__ part) {
    __shared__ __align__(16) char sm[128 * 144 + 64 * 144];   // A 18432B | B 9216B
    char* Asm = sm;
    char* Bsm = sm + 128 * 144;

    const int tid = threadIdx.x;
    const int h = blockIdx.z;
    const float* A = Qg + h * 64 + (size_t)blockIdx.y * 128 * DMODEL;
    const float* B = Kg + h * 64 + (size_t)blockIdx.x * 64 * DMODEL;

    // load + convert: A = 2048 float4, B = 1024 float4
#pragma unroll
    for (int r = 0; r < 8; r++) {
        int idx = tid + r * 256;                          // 0..2047
        int row = idx >> 4, c4 = (idx & 15) * 4;
        float4 v = *(const float4*)&A[(size_t)row * DMODEL + c4];
        *(uint2*)(Asm + row * 144 + c4 * 2) =
            make_uint2(packbf(v.x, v.y), packbf(v.z, v.w));
    }
#pragma unroll
    for (int r = 0; r < 4; r++) {
        int idx = tid + r * 256;                          // 0..1023
        int row = idx >> 4, c4 = (idx & 15) * 4;
        float4 v = *(const float4*)&B[(size_t)row * DMODEL + c4];
        *(uint2*)(Bsm + row * 144 + c4 * 2) =
            make_uint2(packbf(v.x, v.y), packbf(v.z, v.w));
    }
    __syncthreads();

    const int lane = tid & 31, warp = tid >> 5;
    const int wm = (warp & 3) << 5, wn = (warp >> 2) << 5;
    uint32_t sm_u = (uint32_t)__cvta_generic_to_shared(sm);
    const uint32_t aBase = sm_u + (uint32_t)((wm + (lane & 15)) * 144 + (lane >> 4) * 16);
    const uint32_t bBase = sm_u + (uint32_t)(128 * 144) +
                           (uint32_t)((wn + (lane & 15)) * 144 + (lane >> 4) * 16);

    float d[2][4][4];
#pragma unroll
    for (int i = 0; i < 2; i++)
#pragma unroll
        for (int j = 0; j < 4; j++)
#pragma unroll
            for (int q = 0; q < 4; q++) d[i][j][q] = 0.f;

#pragma unroll
    for (int ks = 0; ks < 4; ks++) {
        uint32_t ah[2][4], bh[2][4];
#pragma unroll
        for (int mb = 0; mb < 2; mb++)
            ldsm4(ah[mb], aBase + (uint32_t)(mb * 16 * 144 + ks * 32));
#pragma unroll
        for (int g = 0; g < 2; g++)
            ldsm4(bh[g], bBase + (uint32_t)(g * 16 * 144 + ks * 32));
#pragma unroll
        for (int mb = 0; mb < 2; mb++)
#pragma unroll
            for (int nb = 0; nb < 4; nb++) {
                int g = nb >> 1, j = nb & 1;
                mma_bf16(d[mb][nb], ah[mb], bh[g][j], bh[g][j + 2]);
            }
    }

    // ---- per-column (max, sumexp) over this block's 128 q-rows ----
    const int gc0 = (lane & 3) * 2;
    float cm[8], cs[8];
#pragma unroll
    for (int idx = 0; idx < 8; idx++) {
        int nb = idx >> 1, j = idx & 1;
        float v0 = d[0][nb][j] * 0.125f;
        float v1 = d[0][nb][2 + j] * 0.125f;
        float v2 = d[1][nb][j] * 0.125f;
        float v3 = d[1][nb][2 + j] * 0.125f;
        float m = fmaxf(fmaxf(v0, v1), fmaxf(v2, v3));
        cm[idx] = m;
        cs[idx] = fexp(v0 - m) + fexp(v1 - m) + fexp(v2 - m) + fexp(v3 - m);
    }
#pragma unroll
    for (int off = 4; off <= 16; off <<= 1) {
#pragma unroll
        for (int idx = 0; idx < 8; idx++) {
            float om = __shfl_xor_sync(0xffffffffu, cm[idx], off);
            float os = __shfl_xor_sync(0xffffffffu, cs[idx], off);
            float nm = fmaxf(cm[idx], om);
            cs[idx] = cs[idx] * fexp(cm[idx] - nm) + os * fexp(om - nm);
            cm[idx] = nm;
        }
    }
    __syncthreads();
    float2* psm = (float2*)sm;                            // [4][64], aliases mainloop smem
    if (lane < 4) {
#pragma unroll
        for (int idx = 0; idx < 8; idx++) {
            int nb = idx >> 1, j = idx & 1;
            int col = wn + gc0 + j + nb * 8;
            psm[(warp & 3) * 64 + col] = make_float2(cm[idx], cs[idx]);
        }
    }
    __syncthreads();
    if (tid < 64) {
        float2 a = psm[tid];
        float m = a.x, s = a.y;
#pragma unroll
        for (int w = 1; w < 4; w++) {
            float2 b = psm[w * 64 + tid];
            float nm = fmaxf(m, b.x);
            s = s * fexp(m - nm) + b.y * fexp(b.x - nm);
            m = nm;
        }
        part[((size_t)h * 16 + blockIdx.y) * NTOK + blockIdx.x * 64 + tid] =
            make_float2(m, s);
    }
}

// ---------------- fused lse-combine + corr: corr[h][v] = -sum_m lse[h,m] V[m,h64+v] ----
__global__ void lse_corr_kernel(const float2* __restrict__ part,
                                const float* __restrict__ Vb,
                                float* __restrict__ corr) {
    const int h = blockIdx.x, t = threadIdx.x;            // 256 threads
    __shared__ float slse[NTOK];
    __shared__ float red[256];
#pragma unroll
    for (int i = 0; i < 8; i++) {
        int m = t + 256 * i;
        float mx = -3.0e38f;
        float2 p[16];
#pragma unroll
        for (int s = 0; s < 16; s++) {
            p[s] = part[((size_t)h * 16 + s) * NTOK + m];
            mx = fmaxf(mx, p[s].x);
        }
        float sum = 0.f;
#pragma unroll
        for (int s = 0; s < 16; s++) sum += p[s].y * expf(p[s].x - mx);
        slse[m] = mx + logf(sum);
    }
    __syncthreads();
    int v = t & 63, seg = t >> 6;
    const float* Vp = Vb + h * 64 + v;
    float acc = 0.f;
    for (int m = seg * 512; m < seg * 512 + 512; m++)
        acc = fmaf(slse[m], Vp[(size_t)m * DMODEL], acc);
    red[t] = acc;
    __syncthreads();
    if (t < 64) {
        float tot = red[t] + red[t + 64] + red[t + 128] + red[t + 192];
        corr[h * 64 + t] = -tot;
    }
}

// ---------------- K^T V rank-update partials: per (head, m-chunk of 64) ----------------
__global__ void __launch_bounds__(256)
ktv_kernel(const float* __restrict__ Kg, const float* __restrict__ Vg,
           float* __restrict__ Pk) {
    const int chunk = blockIdx.x, h = blockIdx.y;         // 32 chunks x 8 heads
    const int tid = threadIdx.x;
    const int td = tid & 15, tv = tid >> 4;               // 16x16 thread grid, 4x4 tiles
    __shared__ float sk[32][64], sv[32][64];
    const float* Kp = Kg + h * 64;
    const float* Vp = Vg + h * 64;
    const int m0 = chunk * 64;

    float acc[4][4];
#pragma unroll
    for (int i = 0; i < 4; i++)
#pragma unroll
        for (int j = 0; j < 4; j++) acc[i][j] = 0.f;

    for (int mb = 0; mb < 64; mb += 32) {
        __syncthreads();
#pragma unroll
        for (int r = 0; r < 2; r++) {
            int i = tid + r * 256;                        // float4 index 0..511
            int mi = i >> 4, c4 = (i & 15) * 4;
            *(float4*)&sk[mi][c4] =
                *(const float4*)&Kp[(size_t)(m0 + mb + mi) * DMODEL + c4];
            *(float4*)&sv[mi][c4] =
                *(const float4*)&Vp[(size_t)(m0 + mb + mi) * DMODEL + c4];
        }
        __syncthreads();
#pragma unroll 8
        for (int mi = 0; mi < 32; mi++) {
            float4 kk = *(const float4*)&sk[mi][td * 4];
            float4 vv = *(const float4*)&sv[mi][tv * 4];
            float ka[4] = {kk.x, kk.y, kk.z, kk.w};
            float va[4] = {vv.x, vv.y, vv.z, vv.w};
#pragma unroll
            for (int i = 0; i < 4; i++)
#pragma unroll
                for (int j = 0; j < 4; j++)
                    acc[i][j] = fmaf(ka[i], va[j], acc[i][j]);
        }
    }
    float* P = Pk + ((size_t)h * 32 + chunk) * (DHEAD * DHEAD);
#pragma unroll
    for (int i = 0; i < 4; i++)
        *(float4*)&P[(td * 4 + i) * 64 + tv * 4] = *(float4*)acc[i];
}

// G[h] = 0.125 * sum over 32 chunks (parallel, 8192 threads)
__global__ void ktv_reduce(const float* __restrict__ Pk, float* __restrict__ G) {
    int idx = blockIdx.x * 256 + threadIdx.x;             // 8192 float4's
    int h = idx >> 10, e = (idx & 1023) * 4;
    const float* P = Pk + (size_t)h * 32 * (DHEAD * DHEAD) + e;
    float4 v = *(const float4*)P;
#pragma unroll
    for (int c = 1; c < 32; c++) {
        float4 p = *(const float4*)&P[c * DHEAD * DHEAD];
        v.x += p.x; v.y += p.y; v.z += p.z; v.w += p.w;
    }
    v.x *= 0.125f; v.y *= 0.125f; v.z *= 0.125f; v.w *= 0.125f;
    *(float4*)&G[(size_t)h * DHEAD * DHEAD + e] = v;
}

// ---------------- Wc = blockdiag(G) @ WO, plus bvec = corr @ WO (jt==8 branch) ----------
__global__ void __launch_bounds__(256)
gwo_kernel(const float* __restrict__ G, const float* __restrict__ WO,
           float* __restrict__ Wc, const float* __restrict__ corr,
           float* __restrict__ bvec) {
    const int jt = blockIdx.x, h = blockIdx.y;            // (9 x 8) blocks
    const int tid = threadIdx.x;
    __shared__ float sg[64][65];
    __shared__ float sw[64][68];

    if (jt == 8) {
        // bvec[h*64 + c] = sum_i corr[i] * WO[i][h*64 + c]
        float* red = &sg[0][0];
        int c = tid & 63, seg = tid >> 6;
        float acc = 0.f;
        for (int i = seg * 128; i < seg * 128 + 128; i++)
            acc = fmaf(corr[i], WO[(size_t)i * DMODEL + h * 64 + c], acc);
        red[tid] = acc;
        __syncthreads();
        if (tid < 64)
            bvec[h * 64 + tid] = red[tid] + red[tid + 64] + red[tid + 128] + red[tid + 192];
        return;
    }

    const int tj = tid & 15, td = tid >> 4;
#pragma unroll
    for (int r = 0; r < 16; r++) {
        int i = tid + r * 256;
        int row = i >> 6, c = i & 63;
        sg[row][c] = G[(size_t)h * 4096 + i];
        sw[row][c] = WO[(size_t)(h * 64 + row) * DMODEL + jt * 64 + c];
    }
    __syncthreads();
    float acc[4][4];
#pragma unroll
    for (int i = 0; i < 4; i++)
#pragma unroll
        for (int j = 0; j < 4; j++) acc[i][j] = 0.f;
#pragma unroll 8
    for (int v = 0; v < 64; v++) {
        float a[4], w[4];
#pragma unroll
        for (int i = 0; i < 4; i++) a[i] = sg[td * 4 + i][v];
        float4 w4 = *(const float4*)&sw[v][tj * 4];
        w[0] = w4.x; w[1] = w4.y; w[2] = w4.z; w[3] = w4.w;
#pragma unroll
        for (int i = 0; i < 4; i++)
#pragma unroll
            for (int j = 0; j < 4; j++)
                acc[i][j] = fmaf(a[i], w[j], acc[i][j]);
    }
#pragma unroll
    for (int i = 0; i < 4; i++)
        *(float4*)&Wc[(size_t)(h * 64 + td * 4 + i) * DMODEL + jt * 64 + tj * 4] =
            *(float4*)acc[i];
}

// ---------------- fused split-K reduce + bias + residual + layernorm ----------------
__global__ void __launch_bounds__(128)
reduce_ln(const float* __restrict__ P, int nsplit,
          const float* __restrict__ bias, const float* __restrict__ res,
          const float* __restrict__ g, const float* __restrict__ be,
          float* __restrict__ out) {
    int n = blockIdx.x, t = threadIdx.x;
    size_t base = (size_t)n * 512 + t * 4;
    float4 x = *(const float4*)&P[base];
    for (int s = 1; s < nsplit; s++) {
        float4 p = *(const float4*)&P[(size_t)s * (NTOK * DMODEL) + base];
        x.x += p.x; x.y += p.y; x.z += p.z; x.w += p.w;
    }
    {
        float4 bb4 = *(const float4*)&bias[t * 4];
        x.x += bb4.x; x.y += bb4.y; x.z += bb4.z; x.w += bb4.w;
        float4 r4 = *(const float4*)&res[base];
        x.x += r4.x; x.y += r4.y; x.z += r4.z; x.w += r4.w;
    }
    float s = x.x + x.y + x.z + x.w;
#pragma unroll
    for (int o = 16; o > 0; o >>= 1) s += __shfl_xor_sync(0xffffffffu, s, o);
    __shared__ float r1[4], r2[4];
    if ((t & 31) == 0) r1[t >> 5] = s;
    __syncthreads();
    float mean = (r1[0] + r1[1] + r1[2] + r1[3]) * (1.0f / 512.0f);
    float d0 = x.x - mean, d1 = x.y - mean, d2 = x.z - mean, d3 = x.w - mean;
    float ss = d0 * d0 + d1 * d1 + d2 * d2 + d3 * d3;
#pragma unroll
    for (int o = 16; o > 0; o >>= 1) ss += __shfl_xor_sync(0xffffffffu, ss, o);
    if ((t & 31) == 0) r2[t >> 5] = ss;
    __syncthreads();
    float var = (r2[0] + r2[1] + r2[2] + r2[3]) * (1.0f / 511.0f);
    float rstd = rsqrtf(var);
    float4 gg = *(const float4*)&g[base];
    float4 bb = *(const float4*)&be[base];
    float4 o4;
    o4.x = fmaf(gg.x * rstd, d0, bb.x);
    o4.y = fmaf(gg.y * rstd, d1, bb.y);
    o4.z = fmaf(gg.z * rstd, d2, bb.z);
    o4.w = fmaf(gg.w * rstd, d3, bb.w);
    *(float4*)&out[base] = o4;
}

// ---------------- orchestration (stream fork/join; device work identical every call) ----
extern "C" void kernel_launch(void* const* d_in, const int* in_sizes, int n_in,
                              void* d_out, int out_size) {
    const int* ids = (const int*)d_in[0];
    const float* E = (const float*)d_in[1];
    const float* WQ = (const float*)d_in[2];
    const float* WK = (const float*)d_in[3];
    const float* WV = (const float*)d_in[4];
    const float* WO = (const float*)d_in[5];
    const float* ln1g = (const float*)d_in[6];
    const float* ln1b = (const float*)d_in[7];
    const float* W1 = (const float*)d_in[8];
    const float* b1 = (const float*)d_in[9];
    const float* W2 = (const float*)d_in[10];
    const float* b2 = (const float*)d_in[11];
    const float* ln2g = (const float*)d_in[12];
    const float* ln2b = (const float*)d_in[13];
    float* out = (float*)d_out;
    (void)in_sizes; (void)n_in; (void)out_size;

    // Host-side resources only (no device memory); created once. The captured
    // device work is identical on every call.
    static cudaStream_t s2 = []() {
        cudaStream_t s;
        cudaStreamCreateWithFlags(&s, cudaStreamNonBlocking);
        return s;
    }();
    static cudaEvent_t evF[NLAYER], evJ[NLAYER];
    static bool evInit = []() {
        for (int l = 0; l < NLAYER; l++) {
            cudaEventCreateWithFlags(&evF[l], cudaEventDisableTiming);
            cudaEventCreateWithFlags(&evJ[l], cudaEventDisableTiming);
        }
        return true;
    }();
    (void)evInit;

    float *X, *QKV, *corr, *bvec, *KVp, *G, *Wc, *Z, *F, *P;
    float2* part;
    cudaGetSymbolAddress((void**)&X, g_X);
    cudaGetSymbolAddress((void**)&QKV, g_QKV);
    cudaGetSymbolAddress((void**)&part, g_part);
    cudaGetSymbolAddress((void**)&corr, g_corr);
    cudaGetSymbolAddress((void**)&bvec, g_bvec);
    cudaGetSymbolAddress((void**)&KVp, g_KVp);
    cudaGetSymbolAddress((void**)&G, g_G);
    cudaGetSymbolAddress((void**)&Wc, g_Wc);
    cudaGetSymbolAddress((void**)&Z, g_Z);
    cudaGetSymbolAddress((void**)&F, g_F);
    cudaGetSymbolAddress((void**)&P, g_P);
    float* Q = QKV;
    float* Kb = QKV + NTOK * DMODEL;
    float* Vb = QKV + 2 * NTOK * DMODEL;

    embed_pe<<<NTOK, 128>>>(ids, E, X);

    for (int l = 0; l < NLAYER; l++) {
        const float* WQl = WQ + (size_t)l * NH * DMODEL * DHEAD;
        const float* WKl = WK + (size_t)l * NH * DMODEL * DHEAD;
        const float* WVl = WV + (size_t)l * NH * DMODEL * DHEAD;
        const float* WOl = WO + (size_t)l * DMODEL * DMODEL;
        const float* W1l = W1 + (size_t)l * DMODEL * DFFN;
        const float* b1l = b1 + (size_t)l * DFFN;
        const float* W2l = W2 + (size_t)l * DFFN * DMODEL;
        const float* b2l = b2 + (size_t)l * DMODEL;
        size_t lnOff = (size_t)l * NTOK * DMODEL;

        // ---- fused QKV projections: bz = op*8 + head ----
        gemm_tc<false, true, false><<<dim3(1, 16, 24), 256>>>(
            X, WQl, QKV, DMODEL, DMODEL, DHEAD, DMODEL,
            0LL, (long long)DMODEL * DHEAD, 0LL,
            nullptr, 0, nullptr, 0, 0LL, 1.0f, WKl, WVl, nullptr, 1, 1);

        // ---- fork: K^T V chain on side stream, lse chain on main stream ----
        cudaEventRecord(evF[l], 0);
        cudaStreamWaitEvent(s2, evF[l], 0);

        ktv_kernel<<<dim3(32, 8), 256, 0, s2>>>(Kb, Vb, KVp);
        ktv_reduce<<<32, 256, 0, s2>>>(KVp, G);
        cudaEventRecord(evJ[l], s2);

        qk_lse<<<dim3(32, 16, 8), 256>>>(Q, Kb, part);
        lse_corr_kernel<<<NH, 256>>>(part, Vb, corr);

        // ---- join before gwo (needs G from s2 and corr from main) ----
        cudaStreamWaitEvent(0, evJ[l], 0);
        gwo_kernel<<<dim3(9, 8), 256>>>(G, WOl, Wc, corr, bvec);

        // ---- Z = LN1(Q Wc + bvec + X) (split-K x2, fused reduce+LN) ----
        gemm_tc<false, false, true><<<dim3(8, 16, 2), 256>>>(
            Q, Wc, nullptr, DMODEL, DMODEL, DMODEL, 0,
            0LL, 0LL, 0LL,
            nullptr, 0, nullptr, 0, 0LL, 1.0f, nullptr, nullptr, P, 2, 1);
        reduce_ln<<<NTOK, 128>>>(P, 2, bvec, X, ln1g + lnOff, ln1b + lnOff, Z);

        // ---- F = relu(Z @ W1 + b1) ----
        gemm_tc<true, false, false><<<dim3(32, 16, 1), 256>>>(
            Z, W1l, F, DMODEL, DMODEL, DFFN, DFFN,
            0LL, 0LL, 0LL,
            b1l, 0, nullptr, 0, 0LL, 1.0f, nullptr, nullptr, nullptr, 1, 1);

        // ---- X = LN2(F @ W2 + b2 + Z) (split-K x2, fused reduce+LN) ----
        gemm_tc<false, false, true><<<dim3(8, 16, 2), 256>>>(
            F, W2l, nullptr, DFFN, DFFN, DMODEL, 0,
            0LL, 0LL, 0LL,
            nullptr, 0, nullptr, 0, 0LL, 1.0f, nullptr, nullptr, P, 2, 1);
        reduce_ln<<<NTOK, 128>>>(P, 2, b2l, Z, ln2g + lnOff, ln2b + lnOff,
                                 (l == NLAYER - 1) ? out : X);
    }
}